// round 3
// baseline (speedup 1.0000x reference)
#include <cuda_runtime.h>
#include <cuda_bf16.h>

#define LL 512
#define DD 512
#define HH 512

// ---------------- device scratch ----------------
__device__ float g_u[LL * DD];
__device__ float g_w[LL * DD];
__device__ float g_e[LL * LL];
__device__ float g_a[LL * LL];
__device__ float g_c[LL * DD];
__device__ float g_gi_f[LL * 3 * HH];
__device__ float g_gi_b[LL * 3 * HH];
__device__ float g_h[2][2][HH];              // [dir][parity][h]
__device__ unsigned int g_ctr[2][LL];        // [dir][step]

__device__ __forceinline__ float sigm_(float x) {
    return __fdividef(1.f, 1.f + __expf(-x));
}
__device__ __forceinline__ float tanh_(float x) {
    return 1.f - __fdividef(2.f, __expf(x + x) + 1.f);
}
__device__ __forceinline__ unsigned int ld_acq(const unsigned int* p) {
    unsigned int v;
    asm volatile("ld.acquire.gpu.global.u32 %0, [%1];" : "=r"(v) : "l"(p) : "memory");
    return v;
}
__device__ __forceinline__ void red_rel(unsigned int* p) {
    asm volatile("red.release.gpu.global.add.u32 [%0], %1;" :: "l"(p), "r"(1u) : "memory");
}

// ---------------- init (zero counters + h0) ----------------
__global__ void init_zero() {
    int i = blockIdx.x * 1024 + threadIdx.x;
    if (i < 1024) ((unsigned int*)g_ctr)[i] = 0u;
    if (i < 2048) ((float*)g_h)[i] = 0.f;
}

// ---------------- generic GEMM ----------------
// C[M,N] = concat(A0[:,0:K0], A1[:,0:K-K0]) * op(B) + bias
// transB=1: B is [N,K] row-major (use B^T). transB=0: B is [K,N].
__global__ void gemm_k(const float* __restrict__ A0, const float* __restrict__ A1,
                       int K0, const float* __restrict__ B,
                       const float* __restrict__ bias, float* __restrict__ C,
                       int N, int K, int transB) {
    __shared__ __align__(16) float As[16][68];
    __shared__ __align__(16) float Bs[16][68];
    const int tid = threadIdx.x;
    const int m0 = blockIdx.y * 64, n0 = blockIdx.x * 64;
    const int tm = (tid >> 4) * 4, tn = (tid & 15) * 4;
    const int K1 = K - K0;
    float acc[4][4] = {};
    for (int k0 = 0; k0 < K; k0 += 16) {
#pragma unroll
        for (int i = 0; i < 4; i++) {
            int e = tid + 256 * i;
            {   // A tile: As[kk][row]
                int kk = e & 15, row = e >> 4, gk = k0 + kk;
                As[kk][row] = (gk < K0) ? A0[(m0 + row) * K0 + gk]
                                        : A1[(m0 + row) * K1 + gk - K0];
            }
            if (transB) {
                int kk = e & 15, row = e >> 4;
                Bs[kk][row] = B[(size_t)(n0 + row) * K + k0 + kk];
            } else {
                int n = e & 63, kk = e >> 6;
                Bs[kk][n] = B[(size_t)(k0 + kk) * N + n0 + n];
            }
        }
        __syncthreads();
#pragma unroll
        for (int kk = 0; kk < 16; kk++) {
            float4 a = *(const float4*)&As[kk][tm];
            float4 b = *(const float4*)&Bs[kk][tn];
            float av[4] = {a.x, a.y, a.z, a.w};
            float bv[4] = {b.x, b.y, b.z, b.w};
#pragma unroll
            for (int i = 0; i < 4; i++)
#pragma unroll
                for (int j = 0; j < 4; j++)
                    acc[i][j] = fmaf(av[i], bv[j], acc[i][j]);
        }
        __syncthreads();
    }
#pragma unroll
    for (int i = 0; i < 4; i++)
#pragma unroll
        for (int j = 0; j < 4; j++) {
            float b = bias ? bias[n0 + tn + j] : 0.f;
            C[(size_t)(m0 + tm + i) * N + n0 + tn + j] = acc[i][j] + b;
        }
}

// ---------------- e[t,j] = sum_d tanh(u[j,d]+w[t,d]) * v[j,d] ----------------
__global__ void attn_e(const float* __restrict__ v) {
    __shared__ float us[32][33], vs[32][33], ws[16][33];
    const int tx = threadIdx.x, ty = threadIdx.y;   // tx: local j, ty: local t
    const int j0 = blockIdx.x * 32, t0 = blockIdx.y * 16;
    float acc = 0.f;
    for (int d0 = 0; d0 < DD; d0 += 32) {
        us[ty][tx]      = g_u[(j0 + ty) * DD + d0 + tx];
        us[ty + 16][tx] = g_u[(j0 + ty + 16) * DD + d0 + tx];
        vs[ty][tx]      = v[(j0 + ty) * DD + d0 + tx];
        vs[ty + 16][tx] = v[(j0 + ty + 16) * DD + d0 + tx];
        ws[ty][tx]      = g_w[(t0 + ty) * DD + d0 + tx];
        __syncthreads();
#pragma unroll
        for (int dd = 0; dd < 32; dd++) {
            float x = us[tx][dd] + ws[ty][dd];
            float th = 1.f - __fdividef(2.f, __expf(x + x) + 1.f);
            acc = fmaf(th, vs[tx][dd], acc);
        }
        __syncthreads();
    }
    g_e[(t0 + ty) * LL + j0 + tx] = acc;
}

// ---------------- softmax rows of g_e -> g_a ----------------
__global__ void softmax_rows() {
    __shared__ float red[16];
    __shared__ float bval;
    const int t = blockIdx.x, tid = threadIdx.x, w = tid >> 5, l = tid & 31;
    float x = g_e[t * LL + tid];
    float m = x;
#pragma unroll
    for (int o = 16; o; o >>= 1) m = fmaxf(m, __shfl_xor_sync(~0u, m, o));
    if (l == 0) red[w] = m;
    __syncthreads();
    if (tid == 0) {
        float mm = red[0];
#pragma unroll
        for (int i = 1; i < 16; i++) mm = fmaxf(mm, red[i]);
        bval = mm;
    }
    __syncthreads();
    float p = __expf(x - bval);
    float s = p;
    __syncthreads();
#pragma unroll
    for (int o = 16; o; o >>= 1) s += __shfl_xor_sync(~0u, s, o);
    if (l == 0) red[w] = s;
    __syncthreads();
    if (tid == 0) {
        float ss = red[0];
#pragma unroll
        for (int i = 1; i < 16; i++) ss += red[i];
        bval = ss;
    }
    __syncthreads();
    g_a[t * LL + tid] = __fdividef(p, bval);
}

// ---------------- bidirectional GRU scan ----------------
// 64 CTAs: dir = bid>>5, each CTA owns 16 h-elements. 512 thr: warp = h-elem,
// lane covers k = lane + 32*i. whh rows register-resident.
__global__ void __launch_bounds__(512, 1) gru_scan(
    const float* __restrict__ whh_f, const float* __restrict__ bhh_f,
    const float* __restrict__ whh_b, const float* __restrict__ bhh_b,
    float* __restrict__ out) {
    const int dir = blockIdx.x >> 5, cta = blockIdx.x & 31;
    const int wrp = threadIdx.x >> 5, lane = threadIdx.x & 31;
    const int j = cta * 16 + wrp;  // global h index
    const float* whh = dir ? whh_b : whh_f;
    const float* bhh = dir ? bhh_b : bhh_f;
    const float* gi = dir ? g_gi_b : g_gi_f;
    unsigned int* ctr = g_ctr[dir];

    float wr[16], wz[16], wn[16];
#pragma unroll
    for (int i = 0; i < 16; i++) {
        int k = lane + 32 * i;
        wr[i] = whh[(size_t)j * HH + k];
        wz[i] = whh[(size_t)(HH + j) * HH + k];
        wn[i] = whh[(size_t)(2 * HH + j) * HH + k];
    }
    const float bhr = bhh[j], bhz = bhh[HH + j], bhn = bhh[2 * HH + j];

    for (int s = 0; s < LL; s++) {
        const int t = dir ? (LL - 1 - s) : s;
        const float* hp = g_h[dir][s & 1];
        float* hn = g_h[dir][(s + 1) & 1];
        float aR = 0.f, aZ = 0.f, aN = 0.f;
#pragma unroll
        for (int i = 0; i < 16; i++) {
            float hv = __ldcg(&hp[lane + 32 * i]);
            aR = fmaf(wr[i], hv, aR);
            aZ = fmaf(wz[i], hv, aZ);
            aN = fmaf(wn[i], hv, aN);
        }
#pragma unroll
        for (int o = 16; o; o >>= 1) {
            aR += __shfl_xor_sync(~0u, aR, o);
            aZ += __shfl_xor_sync(~0u, aZ, o);
            aN += __shfl_xor_sync(~0u, aN, o);
        }
        if (lane == 0) {
            const float* gt = gi + (size_t)t * (3 * HH);
            float r = sigm_(gt[j] + aR + bhr);
            float z = sigm_(gt[HH + j] + aZ + bhz);
            float n = tanh_(gt[2 * HH + j] + r * (aN + bhn));
            float hprev = __ldcg(&hp[j]);
            float hnew = (1.f - z) * n + z * hprev;
            __stcg(&hn[j], hnew);
            out[(size_t)t * (2 * HH) + dir * HH + j] = hnew;
        }
        __syncthreads();
        if (threadIdx.x == 0) {
            red_rel(&ctr[s]);
            while (ld_acq(&ctr[s]) < 32u) { }
        }
        __syncthreads();
    }
}

// ---------------- launch ----------------
extern "C" void kernel_launch(void* const* d_in, const int* in_sizes, int n_in,
                              void* d_out, int out_size) {
    const float* v     = (const float*)d_in[0];
    const float* w1    = (const float*)d_in[1];
    const float* b1    = (const float*)d_in[2];
    const float* w2    = (const float*)d_in[3];
    const float* b2    = (const float*)d_in[4];
    const float* wih_f = (const float*)d_in[5];
    const float* whh_f = (const float*)d_in[6];
    const float* bih_f = (const float*)d_in[7];
    const float* bhh_f = (const float*)d_in[8];
    const float* wih_b = (const float*)d_in[9];
    const float* whh_b = (const float*)d_in[10];
    const float* bih_b = (const float*)d_in[11];
    const float* bhh_b = (const float*)d_in[12];
    float* out = (float*)d_out;

    float *pu, *pw, *pe_unused, *pa, *pc, *pgf, *pgb;
    cudaGetSymbolAddress((void**)&pu, g_u);
    cudaGetSymbolAddress((void**)&pw, g_w);
    cudaGetSymbolAddress((void**)&pa, g_a);
    cudaGetSymbolAddress((void**)&pc, g_c);
    cudaGetSymbolAddress((void**)&pgf, g_gi_f);
    cudaGetSymbolAddress((void**)&pgb, g_gi_b);
    (void)pe_unused;

    init_zero<<<2, 1024>>>();

    dim3 b256(256);
    // u = v@w1^T + b1 ; w = v@w2^T + b2
    gemm_k<<<dim3(8, 8), b256>>>(v, v, 512, w1, b1, pu, 512, 512, 1);
    gemm_k<<<dim3(8, 8), b256>>>(v, v, 512, w2, b2, pw, 512, 512, 1);
    // e
    attn_e<<<dim3(16, 32), dim3(32, 16)>>>(v);
    // softmax
    softmax_rows<<<512, 512>>>();
    // c = a @ v  (NN)
    gemm_k<<<dim3(8, 8), b256>>>(pa, pa, 512, v, nullptr, pc, 512, 512, 0);
    // gi = [v|c] @ wih^T + bih
    gemm_k<<<dim3(24, 8), b256>>>(v, pc, 512, wih_f, bih_f, pgf, 1536, 1024, 1);
    gemm_k<<<dim3(24, 8), b256>>>(v, pc, 512, wih_b, bih_b, pgb, 1536, 1024, 1);
    // GRU scan (both directions concurrently)
    gru_scan<<<64, 512>>>(whh_f, bhh_f, whh_b, bhh_b, out);
}

// round 4
// speedup vs baseline: 1.1652x; 1.1652x over previous
#include <cuda_runtime.h>
#include <cuda_bf16.h>

#define LL 512
#define DD 512
#define HH 512

typedef unsigned long long ull;

// ---------------- device scratch ----------------
__device__ float g_u[LL * DD];
__device__ float g_w[LL * DD];
__device__ float g_e[LL * LL];
__device__ float g_a[LL * LL];
__device__ float g_c[LL * DD];
__device__ float g_gi_f[LL * 3 * HH];
__device__ float g_gi_b[LL * 3 * HH];
__device__ float g_h[2][2][HH];               // [dir][parity][h]
__device__ unsigned int g_flag[2][32][32];    // [dir][producer cta][pad to 128B]

__device__ __forceinline__ float sigm_(float x) {
    return __fdividef(1.f, 1.f + __expf(-x));
}
__device__ __forceinline__ float tanh_(float x) {
    return 1.f - __fdividef(2.f, __expf(x + x) + 1.f);
}
__device__ __forceinline__ unsigned int ld_acq(const unsigned int* p) {
    unsigned int v;
    asm volatile("ld.acquire.gpu.global.u32 %0, [%1];" : "=r"(v) : "l"(p) : "memory");
    return v;
}
__device__ __forceinline__ void st_rel(unsigned int* p, unsigned int v) {
    asm volatile("st.release.gpu.global.u32 [%0], %1;" :: "l"(p), "r"(v) : "memory");
}
__device__ __forceinline__ void ffma2(ull& d, ull a, ull b) {
    asm("fma.rn.f32x2 %0, %1, %2, %0;" : "+l"(d) : "l"(a), "l"(b));
}
__device__ __forceinline__ ull packff(float x) {
    ull r; asm("mov.b64 %0, {%1, %1};" : "=l"(r) : "f"(x)); return r;
}
__device__ __forceinline__ float2 unpk(ull v) {
    float2 f; asm("mov.b64 {%0, %1}, %2;" : "=f"(f.x), "=f"(f.y) : "l"(v)); return f;
}

// ---------------- init (zero flags + h0) ----------------
__global__ void init_zero() {
    int i = blockIdx.x * 1024 + threadIdx.x;
    if (i < 2048) ((unsigned int*)g_flag)[i] = 0u;
    if (i < 2048) ((float*)g_h)[i] = 0.f;
}

// ---------------- GEMM core (f32x2 packed) ----------------
// C[M,N] = concat(A0[:,0:K0], A1[:,0:K-K0]) * op(B) + bias
// transB=1: B is [N,K] row-major. transB=0: B is [K,N].
__device__ __forceinline__ void gemm_core(
    const float* __restrict__ A0, const float* __restrict__ A1, int K0,
    const float* __restrict__ B, const float* __restrict__ bias,
    float* __restrict__ C, int N, int K, int transB)
{
    __shared__ __align__(16) float As[16][68];
    __shared__ __align__(16) float Bs[16][68];
    const int tid = threadIdx.x;
    const int m0 = blockIdx.y * 64, n0 = blockIdx.x * 64;
    const int tm = (tid >> 4) * 4, tn = (tid & 15) * 4;
    const int K1 = K - K0;
    ull acc[4][2] = {};
    for (int k0 = 0; k0 < K; k0 += 16) {
#pragma unroll
        for (int i = 0; i < 4; i++) {
            int e = tid + 256 * i;
            {
                int kk = e & 15, row = e >> 4, gk = k0 + kk;
                As[kk][row] = (gk < K0) ? A0[(m0 + row) * K0 + gk]
                                        : A1[(m0 + row) * K1 + gk - K0];
            }
            if (transB) {
                int kk = e & 15, row = e >> 4;
                Bs[kk][row] = B[(size_t)(n0 + row) * K + k0 + kk];
            } else {
                int n = e & 63, kk = e >> 6;
                Bs[kk][n] = B[(size_t)(k0 + kk) * N + n0 + n];
            }
        }
        __syncthreads();
#pragma unroll
        for (int kk = 0; kk < 16; kk++) {
            float4 a = *(const float4*)&As[kk][tm];
            const ull* bp = (const ull*)&Bs[kk][tn];
            ull b01 = bp[0], b23 = bp[1];
            ull a0 = packff(a.x), a1 = packff(a.y), a2 = packff(a.z), a3 = packff(a.w);
            ffma2(acc[0][0], a0, b01); ffma2(acc[0][1], a0, b23);
            ffma2(acc[1][0], a1, b01); ffma2(acc[1][1], a1, b23);
            ffma2(acc[2][0], a2, b01); ffma2(acc[2][1], a2, b23);
            ffma2(acc[3][0], a3, b01); ffma2(acc[3][1], a3, b23);
        }
        __syncthreads();
    }
#pragma unroll
    for (int i = 0; i < 4; i++) {
        float2 c01 = unpk(acc[i][0]), c23 = unpk(acc[i][1]);
        float* cp = C + (size_t)(m0 + tm + i) * N + n0 + tn;
        float b0 = 0.f, b1 = 0.f, b2 = 0.f, b3 = 0.f;
        if (bias) { b0 = bias[n0+tn]; b1 = bias[n0+tn+1]; b2 = bias[n0+tn+2]; b3 = bias[n0+tn+3]; }
        cp[0] = c01.x + b0; cp[1] = c01.y + b1; cp[2] = c23.x + b2; cp[3] = c23.y + b3;
    }
}

__global__ void gemm_uw(const float* __restrict__ v,
                        const float* __restrict__ w1, const float* __restrict__ b1,
                        const float* __restrict__ w2, const float* __restrict__ b2) {
    if (blockIdx.z == 0) gemm_core(v, v, 512, w1, b1, g_u, 512, 512, 1);
    else                 gemm_core(v, v, 512, w2, b2, g_w, 512, 512, 1);
}
__global__ void gemm_c(const float* __restrict__ v) {
    gemm_core(g_a, g_a, 512, v, nullptr, g_c, 512, 512, 0);
}
__global__ void gemm_gi(const float* __restrict__ v,
                        const float* __restrict__ wf, const float* __restrict__ bf,
                        const float* __restrict__ wb, const float* __restrict__ bb) {
    if (blockIdx.z == 0) gemm_core(v, g_c, 512, wf, bf, g_gi_f, 1536, 1024, 1);
    else                 gemm_core(v, g_c, 512, wb, bb, g_gi_b, 1536, 1024, 1);
}

// ---------------- e[t,j] = sum_d tanh(u[j,d]+w[t,d]) * v[j,d] ----------------
__global__ void attn_e(const float* __restrict__ v) {
    __shared__ float us[32][33], vs[32][33], ws[16][33];
    const int tx = threadIdx.x, ty = threadIdx.y;   // tx: local j, ty: local t
    const int j0 = blockIdx.x * 32, t0 = blockIdx.y * 16;
    float acc = 0.f;
    for (int d0 = 0; d0 < DD; d0 += 32) {
        us[ty][tx]      = g_u[(j0 + ty) * DD + d0 + tx];
        us[ty + 16][tx] = g_u[(j0 + ty + 16) * DD + d0 + tx];
        vs[ty][tx]      = v[(j0 + ty) * DD + d0 + tx];
        vs[ty + 16][tx] = v[(j0 + ty + 16) * DD + d0 + tx];
        ws[ty][tx]      = g_w[(t0 + ty) * DD + d0 + tx];
        __syncthreads();
#pragma unroll
        for (int dd = 0; dd < 32; dd++) {
            float x = us[tx][dd] + ws[ty][dd];
            float th = 1.f - __fdividef(2.f, __expf(x + x) + 1.f);
            acc = fmaf(th, vs[tx][dd], acc);
        }
        __syncthreads();
    }
    g_e[(t0 + ty) * LL + j0 + tx] = acc;
}

// ---------------- softmax rows ----------------
__global__ void softmax_rows() {
    __shared__ float red[16];
    __shared__ float bval;
    const int t = blockIdx.x, tid = threadIdx.x, w = tid >> 5, l = tid & 31;
    float x = g_e[t * LL + tid];
    float m = x;
#pragma unroll
    for (int o = 16; o; o >>= 1) m = fmaxf(m, __shfl_xor_sync(~0u, m, o));
    if (l == 0) red[w] = m;
    __syncthreads();
    if (tid == 0) {
        float mm = red[0];
#pragma unroll
        for (int i = 1; i < 16; i++) mm = fmaxf(mm, red[i]);
        bval = mm;
    }
    __syncthreads();
    float p = __expf(x - bval);
    float s = p;
#pragma unroll
    for (int o = 16; o; o >>= 1) s += __shfl_xor_sync(~0u, s, o);
    if (l == 0) red[w] = s;
    __syncthreads();
    if (tid == 0) {
        float ss = red[0];
#pragma unroll
        for (int i = 1; i < 16; i++) ss += red[i];
        bval = ss;
    }
    __syncthreads();
    g_a[t * LL + tid] = __fdividef(p, bval);
}

// ---------------- bidirectional GRU scan ----------------
// 64 CTAs: dir = bid>>5, 32 producer CTAs per dir, 16 h-outputs each.
// Per-producer flag lines + vectorized poll by warp 0.
__global__ void __launch_bounds__(512, 1) gru_scan(
    const float* __restrict__ whh_f, const float* __restrict__ bhh_f,
    const float* __restrict__ whh_b, const float* __restrict__ bhh_b,
    float* __restrict__ out)
{
    const int dir = blockIdx.x >> 5, cta = blockIdx.x & 31;
    const int wrp = threadIdx.x >> 5, lane = threadIdx.x & 31;
    const int j = cta * 16 + wrp;  // this warp's h index
    const float* whh = dir ? whh_b : whh_f;
    const float* bhh = dir ? bhh_b : bhh_f;
    const float* gi  = dir ? g_gi_b : g_gi_f;

    float wr[16], wz[16], wn[16];
#pragma unroll
    for (int i = 0; i < 16; i++) {
        int k = lane + 32 * i;
        wr[i] = whh[(size_t)j * HH + k];
        wz[i] = whh[(size_t)(HH + j) * HH + k];
        wn[i] = whh[(size_t)(2 * HH + j) * HH + k];
    }
    const float bhr = bhh[j], bhz = bhh[HH + j], bhn = bhh[2 * HH + j];

    for (int s = 0; s < LL; s++) {
        const int t = dir ? (LL - 1 - s) : s;
        // gi prefetch (independent of h) overlaps the poll
        float giR = 0.f, giZ = 0.f, giN = 0.f;
        if (lane == 0) {
            const float* gt = gi + (size_t)t * (3 * HH);
            giR = __ldg(&gt[j]); giZ = __ldg(&gt[HH + j]); giN = __ldg(&gt[2 * HH + j]);
        }
        // wait until all producers have published h_s (s=0: h0 from init)
        if (s > 0 && wrp == 0) {
            const unsigned tgt = (unsigned)s;
            while (__any_sync(0xffffffffu, ld_acq(&g_flag[dir][lane][0]) < tgt)) {}
        }
        __syncthreads();
        const float* hp = g_h[dir][s & 1];
        float* hn = g_h[dir][(s + 1) & 1];
        float aR = 0.f, aZ = 0.f, aN = 0.f;
#pragma unroll
        for (int i = 0; i < 16; i++) {
            float hv = __ldcg(&hp[lane + 32 * i]);
            aR = fmaf(wr[i], hv, aR);
            aZ = fmaf(wz[i], hv, aZ);
            aN = fmaf(wn[i], hv, aN);
        }
#pragma unroll
        for (int o = 16; o; o >>= 1) {
            aR += __shfl_xor_sync(0xffffffffu, aR, o);
            aZ += __shfl_xor_sync(0xffffffffu, aZ, o);
            aN += __shfl_xor_sync(0xffffffffu, aN, o);
        }
        if (lane == 0) {
            float r = sigm_(giR + aR + bhr);
            float z = sigm_(giZ + aZ + bhz);
            float n = tanh_(giN + r * (aN + bhn));
            float hprev = __ldcg(&hp[j]);
            float hnew = (1.f - z) * n + z * hprev;
            __stcg(&hn[j], hnew);
            out[(size_t)t * (2 * HH) + dir * HH + j] = hnew;
        }
        __syncthreads();
        if (threadIdx.x == 0) st_rel(&g_flag[dir][cta][0], (unsigned)(s + 1));
    }
}

// ---------------- launch ----------------
extern "C" void kernel_launch(void* const* d_in, const int* in_sizes, int n_in,
                              void* d_out, int out_size) {
    const float* v     = (const float*)d_in[0];
    const float* w1    = (const float*)d_in[1];
    const float* b1    = (const float*)d_in[2];
    const float* w2    = (const float*)d_in[3];
    const float* b2    = (const float*)d_in[4];
    const float* wih_f = (const float*)d_in[5];
    const float* whh_f = (const float*)d_in[6];
    const float* bih_f = (const float*)d_in[7];
    const float* bhh_f = (const float*)d_in[8];
    const float* wih_b = (const float*)d_in[9];
    const float* whh_b = (const float*)d_in[10];
    const float* bih_b = (const float*)d_in[11];
    const float* bhh_b = (const float*)d_in[12];
    float* out = (float*)d_out;

    init_zero<<<2, 1024>>>();
    gemm_uw<<<dim3(8, 8, 2), 256>>>(v, w1, b1, w2, b2);
    attn_e<<<dim3(16, 32), dim3(32, 16)>>>(v);
    softmax_rows<<<512, 512>>>();
    gemm_c<<<dim3(8, 8), 256>>>(v);
    gemm_gi<<<dim3(24, 8, 2), 256>>>(v, wih_f, bih_f, wih_b, bih_b);
    gru_scan<<<64, 512>>>(whh_f, bhh_f, whh_b, bhh_b, out);
}